// round 17
// baseline (speedup 1.0000x reference)
#include <cuda_runtime.h>
#include <cuda_bf16.h>
#include <cstdint>

#define NPTS 80000          // 100*100*8
#define NG 1025             // 1024 gaussians + 1 synthetic "empty"
#define NC 18
#define THREADS 256
#define TILE 64
#define LOG2E 1.4426950408889634f

// Block tile: 4h x 4w x 8d = 128 points. 2 threads per point (gaussian-split).
// pt = tid & 127: dd = pt&7, ww = (pt>>3)&3, hh = pt>>5. half = tid>>7.

__device__ __forceinline__ void ffma2(uint64_t& acc, uint64_t ab, uint64_t w2) {
    asm("fma.rn.f32x2 %0, %1, %2, %0;" : "+l"(acc) : "l"(ab), "l"(w2));
}
__device__ __forceinline__ uint64_t fadd2(uint64_t a, uint64_t b) {
    uint64_t r;
    asm("add.rn.f32x2 %0, %1, %2;" : "=l"(r) : "l"(a), "l"(b));
    return r;
}
__device__ __forceinline__ float ex2f(float x) {
    float r;
    asm("ex2.approx.ftz.f32 %0, %1;" : "=f"(r) : "f"(x));
    return r;
}
__device__ __forceinline__ float rcpf(float x) {
    float r;
    asm("rcp.approx.ftz.f32 %0, %1;" : "=f"(r) : "f"(x));
    return r;
}

__global__ __launch_bounds__(THREADS, 4) void voxelize(
    const float* __restrict__ means,
    const float* __restrict__ opac,
    const float* __restrict__ scales,
    const float* __restrict__ rots,
    const float* __restrict__ feats,
    const float* __restrict__ empty_scalar,
    float* __restrict__ out)
{
    const int tid = threadIdx.x;
    const int pt = tid & 127;
    const int half = tid >> 7;
    const int bh = blockIdx.x, bw = blockIdx.y;
    const int dd = pt & 7;
    const int ww = (pt >> 3) & 3;
    const int hh = pt >> 5;
    const int h = 4 * bh + hh;
    const int w = 4 * bw + ww;
    const int p = h * 800 + w * 8 + dd;

    // match reference rounding: (i+0.5)*0.8 + lo, no fma contraction
    const float px = __fadd_rn(__fmul_rn((float)h + 0.5f, 0.8f), -40.f);
    const float py = __fadd_rn(__fmul_rn((float)w + 0.5f, 0.8f), -40.f);
    const float pz = __fadd_rn(__fmul_rn((float)dd + 0.5f, 0.8f), -1.f);

    // analytic block bbox (conservative, eps-padded); z center 2.2, half 2.8
    const float EPS = 1e-3f;
    const float bcx = (4.f * (float)bh + 2.f) * 0.8f - 40.f;   // half 1.2
    const float bcy = (4.f * (float)bw + 2.f) * 0.8f - 40.f;   // half 1.2
    const float BH  = 1.2f + EPS;
    const float BHZ = 2.8f + EPS;

    __shared__ unsigned short s_list[NG + 1];
    __shared__ int s_cnt;
    if (tid == 0) s_cnt = 0;
    __syncthreads();

    // ---- block-level compaction: 4 consecutive gaussians per thread,
    //      3+3 LDG.128 instead of 24 LDG.32 ----
    {
        const float4* m4 = (const float4*)means;   // 1024*3 floats = 768 float4
        const float4* s4 = (const float4*)scales;
        const float4 ma = __ldg(m4 + 3 * tid);
        const float4 mb = __ldg(m4 + 3 * tid + 1);
        const float4 mc = __ldg(m4 + 3 * tid + 2);
        const float4 sa = __ldg(s4 + 3 * tid);
        const float4 sb = __ldg(s4 + 3 * tid + 1);
        const float4 sc = __ldg(s4 + 3 * tid + 2);
        const int g0 = 4 * tid;

        if (fabsf(bcx - ma.x) <= BH + 3.f * sa.x &&
            fabsf(bcy - ma.y) <= BH + 3.f * sa.y &&
            fabsf(2.2f - ma.z) <= BHZ + 3.f * sa.z)
            s_list[atomicAdd(&s_cnt, 1)] = (unsigned short)(g0 + 0);

        if (fabsf(bcx - ma.w) <= BH + 3.f * sa.w &&
            fabsf(bcy - mb.x) <= BH + 3.f * sb.x &&
            fabsf(2.2f - mb.y) <= BHZ + 3.f * sb.y)
            s_list[atomicAdd(&s_cnt, 1)] = (unsigned short)(g0 + 1);

        if (fabsf(bcx - mb.z) <= BH + 3.f * sb.z &&
            fabsf(bcy - mb.w) <= BH + 3.f * sb.w &&
            fabsf(2.2f - mc.x) <= BHZ + 3.f * sc.x)
            s_list[atomicAdd(&s_cnt, 1)] = (unsigned short)(g0 + 2);

        if (fabsf(bcx - mc.y) <= BH + 3.f * sc.y &&
            fabsf(bcy - mc.z) <= BH + 3.f * sc.z &&
            fabsf(2.2f - mc.w) <= BHZ + 3.f * sc.w)
            s_list[atomicAdd(&s_cnt, 1)] = (unsigned short)(g0 + 3);

        if (tid == 0)   // synthetic gaussian covers the whole volume: always in
            s_list[atomicAdd(&s_cnt, 1)] = (unsigned short)(NG - 1);
    }
    __syncthreads();
    const int cnt = s_cnt;

    // rec layout (12 floats/row, 3x LDS.128), padded by 1 row for pipelining:
    //   [0..2]=mu [3]=rx | [4]=ry [5]=rz [6]=a00 [7]=a01 | [8]=a02 [9]=a11 [10]=a12 [11]=a22
    // a_ij carry -0.5*log2(e) and off-diagonal 2x folded in (log2 domain).
    // Built directly as inv(cov) = R diag(1/s^2) R^T.
    // feature rows (20 floats) carry opacity folded in: staged_f = opa * f.
    // POOL SIZE INVARIANT: the pool is reused as the cross-half reduction
    // buffer which needs 128*9 u64 = 2304 floats. Staging needs
    // (TILE+1)*12 + TILE*20 = 2061 floats. Pool = 2304 floats = 9216 B.
    __shared__ __align__(16) float s_pool[TILE * 36];
    float* const s_rec = s_pool;                       // [TILE+1][12]
    float* const s_ft  = s_pool + TILE * 12 + 12;      // [TILE][20]

    uint64_t acc2[9];
    #pragma unroll
    for (int c = 0; c < 9; c++) acc2[c] = 0ull;

    for (int t0 = 0; t0 < cnt; t0 += TILE) {
        const int n = min(TILE, cnt - t0);

        // ---- dense staging: tid<n -> record; 128<=tid<128+n -> features ----
        if (tid < n) {
            const int g = s_list[t0 + tid];
            float* rc = s_rec + tid * 12;
            if (g < NG - 1) {
                const float4 q = __ldg((const float4*)rots + g);   // w,x,y,z
                float qw = q.x, qx = q.y, qy = q.z, qz = q.w;
                float inv = rsqrtf(qw * qw + qx * qx + qy * qy + qz * qz);
                qw *= inv; qx *= inv; qy *= inv; qz *= inv;
                float R00 = 1.f - 2.f * (qy * qy + qz * qz);
                float R01 = 2.f * (qx * qy - qw * qz);
                float R02 = 2.f * (qx * qz + qw * qy);
                float R10 = 2.f * (qx * qy + qw * qz);
                float R11 = 1.f - 2.f * (qx * qx + qz * qz);
                float R12 = 2.f * (qy * qz - qw * qx);
                float R20 = 2.f * (qx * qz - qw * qy);
                float R21 = 2.f * (qy * qz + qw * qx);
                float R22 = 1.f - 2.f * (qx * qx + qy * qy);

                const float s0 = __ldg(scales + g * 3 + 0);
                const float s1 = __ldg(scales + g * 3 + 1);
                const float s2 = __ldg(scales + g * 3 + 2);
                const float K = -0.5f * LOG2E;
                const float w0 = K * rcpf(s0 * s0);
                const float w1 = K * rcpf(s1 * s1);
                const float w2v = K * rcpf(s2 * s2);

                const float P00 = R00 * w0, P01 = R01 * w1, P02 = R02 * w2v;
                const float P10 = R10 * w0, P11 = R11 * w1, P12 = R12 * w2v;
                const float P20 = R20 * w0, P21 = R21 * w1, P22 = R22 * w2v;

                rc[0] = __ldg(means + g * 3 + 0);
                rc[1] = __ldg(means + g * 3 + 1);
                rc[2] = __ldg(means + g * 3 + 2);
                rc[3] = 3.f * s0;
                rc[4] = 3.f * s1;
                rc[5] = 3.f * s2;
                rc[6]  = fmaf(P00, R00, fmaf(P01, R01, P02 * R02));          // a00
                rc[7]  = 2.f * fmaf(P00, R10, fmaf(P01, R11, P02 * R12));    // a01
                rc[8]  = 2.f * fmaf(P00, R20, fmaf(P01, R21, P02 * R22));    // a02
                rc[9]  = fmaf(P10, R10, fmaf(P11, R11, P12 * R12));          // a11
                rc[10] = 2.f * fmaf(P10, R20, fmaf(P11, R21, P12 * R22));    // a12
                rc[11] = fmaf(P20, R20, fmaf(P21, R21, P22 * R22));          // a22
            } else {
                rc[0] = 0.f; rc[1] = 0.f; rc[2] = 2.2f;
                rc[3] = 240.f; rc[4] = 240.f; rc[5] = 19.2f;
                rc[6]  = -0.5f * LOG2E / 6400.f;
                rc[7]  = 0.f; rc[8] = 0.f;
                rc[9]  = -0.5f * LOG2E / 6400.f;
                rc[10] = 0.f;
                rc[11] = -0.5f * LOG2E / 40.96f;
            }
        } else if (tid >= 128 && tid < 128 + n) {
            const int s = tid - 128;
            const int g = s_list[t0 + s];
            float* ft = s_ft + s * 20;
            if (g < NG - 1) {
                const float op = __ldg(opac + g);
                const float* fs = feats + (size_t)g * (NC - 1);
                #pragma unroll
                for (int c = 0; c < NC - 1; c++) ft[c] = op * __ldg(fs + c);
                ft[NC - 1] = 0.f;
            } else {
                #pragma unroll
                for (int c = 0; c < NC - 1; c++) ft[c] = 0.f;
                ft[NC - 1] = __ldg(empty_scalar);   // opa = 1
            }
        }
        __syncthreads();

        // ---- eval: software-pipelined over this half's entries ----
        const int nh = (n + 1) >> 1;
        const int lo = half * nh;
        const int hi = min(n, lo + nh);
        if (lo < hi) {
            // preload first record
            float4 v0 = *(const float4*)(s_rec + lo * 12);
            float4 v1 = *(const float4*)(s_rec + lo * 12 + 4);
            float4 v2 = *(const float4*)(s_rec + lo * 12 + 8);
            #pragma unroll 2
            for (int j = lo; j < hi; j++) {
                // prefetch next record (padded row makes j+1 <= TILE safe)
                const float4 n0 = *(const float4*)(s_rec + (j + 1) * 12);
                const float4 n1 = *(const float4*)(s_rec + (j + 1) * 12 + 4);
                const float4 n2 = *(const float4*)(s_rec + (j + 1) * 12 + 8);

                const float dx = px - v0.x;
                const float dy = py - v0.y;
                const float dz = pz - v0.z;
                const bool m = (fabsf(dx) <= v0.w) & (fabsf(dy) <= v1.x) &
                               (fabsf(dz) <= v1.y);
                float t1 = fmaf(v1.w, dy, v1.z * dx);        // a00 dx + a01 dy
                t1 = fmaf(v2.x, dz, t1);                     // + a02 dz
                const float t2 = fmaf(v2.z, dz, v2.y * dy);  // a11 dy + a12 dz
                float arg = v2.w * dz * dz;                  // a22 dz^2
                arg = fmaf(dy, t2, arg);
                arg = fmaf(dx, t1, arg);
                const float wgt = m ? ex2f(arg) : 0.f;       // log2 domain
                uint64_t w2;
                asm("mov.b64 %0, {%1, %1};" : "=l"(w2) : "f"(wgt));
                const uint64_t* f8 = (const uint64_t*)(s_ft + j * 20);
                #pragma unroll
                for (int q = 0; q < 4; q++) {
                    const ulonglong2 fv = ((const ulonglong2*)f8)[q];
                    ffma2(acc2[2 * q + 0], fv.x, w2);
                    ffma2(acc2[2 * q + 1], fv.y, w2);
                }
                ffma2(acc2[8], f8[8], w2);

                v0 = n0; v1 = n1; v2 = n2;   // rotate
            }
        }
        __syncthreads();
    }

    // ---- cross-half reduction through the (now dead) staging pool ----
    uint64_t* const red = (uint64_t*)s_pool;   // 128*9 u64 = 9216 B = pool size
    if (half == 1) {
        uint64_t* r = red + pt * 9;
        #pragma unroll
        for (int c = 0; c < 9; c++) r[c] = acc2[c];
    }
    __syncthreads();
    if (half == 0) {
        const uint64_t* r = red + pt * 9;
        out[p] = 0.f;   // grid_density
        uint64_t* o = (uint64_t*)(out + NPTS + (size_t)p * NC);
        #pragma unroll
        for (int c = 0; c < 9; c++)
            o[c] = fadd2(acc2[c], r[c]);
    }
}

extern "C" void kernel_launch(void* const* d_in, const int* in_sizes, int n_in,
                              void* d_out, int out_size) {
    const float* means        = (const float*)d_in[0];
    const float* opacities    = (const float*)d_in[1];
    const float* scales       = (const float*)d_in[2];
    const float* rotations    = (const float*)d_in[3];
    const float* features     = (const float*)d_in[4];
    const float* empty_scalar = (const float*)d_in[5];
    float* out = (float*)d_out;

    dim3 grid(25, 25);
    voxelize<<<grid, THREADS>>>(means, opacities, scales, rotations,
                                features, empty_scalar, out);
}